// round 3
// baseline (speedup 1.0000x reference)
#include <cuda_runtime.h>

// Problem dims
#define MB 8
#define TT 4000
#define BBCH 128
#define HH 512
#define MT (MB*TT)      // 32000 rows
#define LP (TT+4)       // padded length for deform conv (pad_tot = 4)
#define TC 16           // t-tile for fused offset+deform kernel
#define RNUM (TC+5)     // 21 smem rows (t0-2 .. t0+TC+2)

// ---- scratch (device globals; no allocations allowed) ----
__device__ float g_h[MT * HH];     // prelu(x@W1^T), pre-norm   [M*T, H]
__device__ float g_p[MT * HH];     // prelu2(deform out), pre-norm
__device__ float g_sum1[MB], g_sq1[MB], g_sum2[MB], g_sq2[MB];
__device__ float g_mu1[MB], g_iv1[MB], g_mu2[MB], g_iv2[MB];

// ---- f32x2 packed helpers (FFMA2 path, PTX-only on sm_103a) ----
__device__ __forceinline__ unsigned long long pack2(float lo, float hi) {
    unsigned long long r;
    asm("mov.b64 %0, {%1, %2};" : "=l"(r) : "f"(lo), "f"(hi));
    return r;
}
__device__ __forceinline__ void unpack2(unsigned long long v, float &lo, float &hi) {
    asm("mov.b64 {%0, %1}, %2;" : "=f"(lo), "=f"(hi) : "l"(v));
}
__device__ __forceinline__ void fma2(unsigned long long &d, unsigned long long a, unsigned long long b) {
    asm("fma.rn.f32x2 %0, %1, %2, %0;" : "+l"(d) : "l"(a), "l"(b));
}

// ---------------------------------------------------------------------------
__global__ void zero_stats_kernel() {
    int i = threadIdx.x;
    if (i < MB) { g_sum1[i] = 0.f; g_sq1[i] = 0.f; g_sum2[i] = 0.f; g_sq2[i] = 0.f; }
}

__global__ void finalize1_kernel() {
    int m = threadIdx.x;
    if (m < MB) {
        float n = (float)TT * (float)HH;
        float mu = g_sum1[m] / n;
        float var = g_sq1[m] / n - mu * mu;
        g_mu1[m] = mu;
        g_iv1[m] = 1.0f / sqrtf(var + 1e-8f);
    }
}

__global__ void finalize2_kernel() {
    int m = threadIdx.x;
    if (m < MB) {
        float n = (float)TT * (float)HH;
        float mu = g_sum2[m] / n;
        float var = g_sq2[m] / n - mu * mu;
        g_mu2[m] = mu;
        g_iv2[m] = 1.0f / sqrtf(var + 1e-8f);
    }
}

// ---------------------------------------------------------------------------
// GEMM1: h[row, n] = prelu( sum_k x[row,k] * W1[n,k] )  row<32000, n<512, k<128
// 128x128 tile, 256 threads, 8x8 microtile, packed f32x2 FMAs (row pairs).
// Fused per-sample gLN stats on the prelu'd values.
__global__ void __launch_bounds__(256)
gemm1_kernel(const float* __restrict__ A,   // x [32000,128]
             const float* __restrict__ W,   // conv1_w [512,128]
             const float* __restrict__ prelu_a) {
    __shared__ float As[16][130];
    __shared__ float Bs[16][130];
    __shared__ float red[256];
    const int rowTile = blockIdx.x * 128;
    const int colTile = blockIdx.y * 128;
    const int tx = threadIdx.x & 15;    // col group
    const int ty = threadIdx.x >> 4;    // row group
    const int tid = threadIdx.x;
    unsigned long long acc[4][8];       // [row-pair][col]
#pragma unroll
    for (int i = 0; i < 4; i++)
#pragma unroll
        for (int j = 0; j < 8; j++) acc[i][j] = 0ull;

    for (int k0 = 0; k0 < BBCH; k0 += 16) {
#pragma unroll
        for (int i = 0; i < 8; i++) {
            int e = tid + i * 256;       // 0..2047
            int r = e >> 4, c = e & 15;
            As[c][r] = A[(size_t)(rowTile + r) * BBCH + k0 + c];
            Bs[c][r] = W[(size_t)(colTile + r) * BBCH + k0 + c];
        }
        __syncthreads();
#pragma unroll
        for (int kk = 0; kk < 16; kk++) {
            unsigned long long a[4];
#pragma unroll
            for (int i = 0; i < 4; i++)
                a[i] = *(const unsigned long long*)&As[kk][ty * 8 + 2 * i];
#pragma unroll
            for (int j = 0; j < 8; j++) {
                float bv = Bs[kk][tx * 8 + j];
                unsigned long long ub = pack2(bv, bv);
#pragma unroll
                for (int i = 0; i < 4; i++) fma2(acc[i][j], a[i], ub);
            }
        }
        __syncthreads();
    }

    const float a = prelu_a[0];
    const int m0 = rowTile / TT;
    const int m1 = (rowTile + 127) / TT;
    float s[2] = {0.f, 0.f}, q[2] = {0.f, 0.f};
#pragma unroll
    for (int i = 0; i < 4; i++) {
#pragma unroll
        for (int lh = 0; lh < 2; lh++) {
            int row = rowTile + ty * 8 + 2 * i + lh;
            int bin = (row / TT) - m0;
#pragma unroll
            for (int j = 0; j < 8; j++) {
                float lo, hi;
                unpack2(acc[i][j], lo, hi);
                float v = lh ? hi : lo;
                v = v >= 0.f ? v : a * v;
                g_h[(size_t)row * HH + colTile + tx * 8 + j] = v;
                s[bin] += v;
                q[bin] += v * v;
            }
        }
    }
    int nb = (m1 > m0) ? 2 : 1;
    for (int b = 0; b < nb; b++) {
        red[tid] = s[b]; __syncthreads();
        for (int off = 128; off > 0; off >>= 1) {
            if (tid < off) red[tid] += red[tid + off];
            __syncthreads();
        }
        if (tid == 0) atomicAdd(&g_sum1[m0 + b], red[0]);
        __syncthreads();
        red[tid] = q[b]; __syncthreads();
        for (int off = 128; off > 0; off >>= 1) {
            if (tid < off) red[tid] += red[tid + off];
            __syncthreads();
        }
        if (tid == 0) atomicAdd(&g_sq1[m0 + b], red[0]);
        __syncthreads();
    }
}

// ---------------------------------------------------------------------------
// Fused offsets + deformable depthwise conv, t-tiled with smem row cache.
// One block = (m, 16 consecutive t). Normalized h rows staged once in smem.
__global__ void __launch_bounds__(256)
offdef_kernel(const float* __restrict__ odww,  // off_dw_w [512,3]
              const float* __restrict__ odc_a,
              const float* __restrict__ opww,  // off_pw_w [3,512]
              const float* __restrict__ opc_a,
              const float* __restrict__ dww,   // dw_w [512,3]
              const float* __restrict__ dwb,   // dw_b [512]
              const float* __restrict__ a2p,   // prelu2_a
              const float* __restrict__ gam,   // norm1_g
              const float* __restrict__ bet) { // norm1_b
    __shared__ float sgc[HH];
    __shared__ float sbc[HH];
    __shared__ float rows[RNUM][HH];
    __shared__ float w0[TC][3], w1[TC][3];
    __shared__ int   i0[TC][3], i1[TC][3];
    __shared__ float red[256];

    const int m  = blockIdx.y;
    const int t0 = blockIdx.x * TC;
    const int tid = threadIdx.x;
    const float mu = g_mu1[m], iv = g_iv1[m];

    for (int c = tid; c < HH; c += 256) {
        float gc = gam[c] * iv;
        sgc[c] = gc;
        sbc[c] = bet[c] - gc * mu;
    }
    __syncthreads();

    // Stage normalized rows for source times t0-2 .. t0+18 (reflect mapped).
    const float* base = g_h + (size_t)m * TT * HH;
    for (int e = tid; e < RNUM * HH; e += 256) {
        int j = e >> 9, c = e & 511;
        int src = t0 - 2 + j;
        if (src < 0) src = -src;
        if (src >= TT) src = 2 * TT - 2 - src;
        rows[j][c] = sgc[c] * base[(size_t)src * HH + c] + sbc[c];
    }
    __syncthreads();

    // Phase 1: offsets. 16 threads per t (txx = channel lane).
    {
        const int tyy = tid >> 4, txx = tid & 15;
        const int t = t0 + tyy;
        const float* r0 = rows[tyy + 1];   // time t-1
        const float* r1 = rows[tyy + 2];   // time t
        const float* r2 = rows[tyy + 3];   // time t+1
        const float aodc = odc_a[0];
        float s0 = 0.f, s1 = 0.f, s2 = 0.f;
        for (int c = txx; c < HH; c += 16) {
            float od = odww[c * 3] * r0[c] + odww[c * 3 + 1] * r1[c] + odww[c * 3 + 2] * r2[c];
            od = od >= 0.f ? od : aodc * od;
            s0 += opww[c] * od;
            s1 += opww[HH + c] * od;
            s2 += opww[2 * HH + c] * od;
        }
#pragma unroll
        for (int o = 8; o > 0; o >>= 1) {
            s0 += __shfl_down_sync(0xffffffffu, s0, o, 16);
            s1 += __shfl_down_sync(0xffffffffu, s1, o, 16);
            s2 += __shfl_down_sync(0xffffffffu, s2, o, 16);
        }
        if (txx == 0) {
            const float aopc = opc_a[0];
            float off[3];
            off[0] = s0 >= 0.f ? s0 : aopc * s0;
            off[1] = s1 >= 0.f ? s1 : aopc * s1;
            off[2] = s2 >= 0.f ? s2 : aopc * s2;
#pragma unroll
            for (int k = 0; k < 3; k++) {
                float tpos = (float)t + 2.0f * (float)k + off[k];
                tpos = fminf(fmaxf(tpos, (float)t), (float)(t + 4));
                int U = (int)floorf(tpos);
                U = min(U, LP - 2);
                float Uf = (float)U;
                w0[tyy][k] = fmaxf(1.0f - fabsf(Uf - tpos), 0.0f);
                w1[tyy][k] = fmaxf(1.0f - fabsf(Uf + 1.0f - tpos), 0.0f);
                i0[tyy][k] = U - t0;        // smem row for xp[U]
                i1[tyy][k] = U + 1 - t0;    // smem row for xp[U+1]
            }
        }
    }
    __syncthreads();

    // Phase 2: deformable depthwise conv + bias + PReLU2 + gLN2 stats.
    const float a2 = a2p[0];
    float lsum = 0.f, lsq = 0.f;
    for (int e = tid; e < TC * HH; e += 256) {
        int tyy = e >> 9, h = e & 511;
        float y = dwb[h];
#pragma unroll
        for (int k = 0; k < 3; k++) {
            float v = w0[tyy][k] * rows[i0[tyy][k]][h] + w1[tyy][k] * rows[i1[tyy][k]][h];
            y += dww[h * 3 + k] * v;
        }
        float p = y >= 0.f ? y : a2 * y;
        g_p[(size_t)(m * TT + t0 + tyy) * HH + h] = p;
        lsum += p;
        lsq += p * p;
    }
    red[tid] = lsum; __syncthreads();
    for (int o = 128; o > 0; o >>= 1) {
        if (tid < o) red[tid] += red[tid + o];
        __syncthreads();
    }
    if (tid == 0) atomicAdd(&g_sum2[m], red[0]);
    __syncthreads();
    red[tid] = lsq; __syncthreads();
    for (int o = 128; o > 0; o >>= 1) {
        if (tid < o) red[tid] += red[tid + o];
        __syncthreads();
    }
    if (tid == 0) atomicAdd(&g_sq2[m], red[0]);
}

// ---------------------------------------------------------------------------
// GEMM2: out[row,b] = x[row,b] + sum_h W2[b,h] * gln2(g_p[row,h])
// 128x128 tile (grid.y=1), packed f32x2 FMAs, gLN folded into A-tile load.
__global__ void __launch_bounds__(256)
gemm2_kernel(const float* __restrict__ W,    // pw_w [128,512]
             const float* __restrict__ gam,  // norm2_g
             const float* __restrict__ bet,  // norm2_b
             const float* __restrict__ X,    // residual x [32000,128]
             float* __restrict__ out) {
    __shared__ float As[16][130];
    __shared__ float Bs[16][130];
    const int rowTile = blockIdx.x * 128;
    const int colTile = blockIdx.y * 128;
    const int tx = threadIdx.x & 15;
    const int ty = threadIdx.x >> 4;
    const int tid = threadIdx.x;
    unsigned long long acc[4][8];
#pragma unroll
    for (int i = 0; i < 4; i++)
#pragma unroll
        for (int j = 0; j < 8; j++) acc[i][j] = 0ull;

    for (int k0 = 0; k0 < HH; k0 += 16) {
#pragma unroll
        for (int i = 0; i < 8; i++) {
            int e = tid + i * 256;
            int r = e >> 4, c = e & 15;
            int row = rowTile + r;
            int mm = row / TT;
            int k = k0 + c;
            float v = g_p[(size_t)row * HH + k];
            float gc = gam[k] * g_iv2[mm];
            As[c][r] = gc * v + (bet[k] - gc * g_mu2[mm]);
            Bs[c][r] = W[(size_t)(colTile + r) * HH + k];
        }
        __syncthreads();
#pragma unroll
        for (int kk = 0; kk < 16; kk++) {
            unsigned long long a[4];
#pragma unroll
            for (int i = 0; i < 4; i++)
                a[i] = *(const unsigned long long*)&As[kk][ty * 8 + 2 * i];
#pragma unroll
            for (int j = 0; j < 8; j++) {
                float bv = Bs[kk][tx * 8 + j];
                unsigned long long ub = pack2(bv, bv);
#pragma unroll
                for (int i = 0; i < 4; i++) fma2(acc[i][j], a[i], ub);
            }
        }
        __syncthreads();
    }
#pragma unroll
    for (int i = 0; i < 4; i++) {
#pragma unroll
        for (int lh = 0; lh < 2; lh++) {
            int row = rowTile + ty * 8 + 2 * i + lh;
#pragma unroll
            for (int j = 0; j < 8; j++) {
                int col = colTile + tx * 8 + j;
                float lo, hi;
                unpack2(acc[i][j], lo, hi);
                float v = lh ? hi : lo;
                out[(size_t)row * BBCH + col] = v + X[(size_t)row * BBCH + col];
            }
        }
    }
}

// ---------------------------------------------------------------------------
extern "C" void kernel_launch(void* const* d_in, const int* in_sizes, int n_in,
                              void* d_out, int out_size) {
    (void)in_sizes; (void)n_in; (void)out_size;
    const float* x        = (const float*)d_in[0];
    const float* conv1_w  = (const float*)d_in[1];
    const float* prelu1_a = (const float*)d_in[2];
    const float* norm1_g  = (const float*)d_in[3];
    const float* norm1_b  = (const float*)d_in[4];
    const float* off_dw_w = (const float*)d_in[5];
    const float* odc_a    = (const float*)d_in[6];
    const float* off_pw_w = (const float*)d_in[7];
    const float* opc_a    = (const float*)d_in[8];
    const float* dw_w     = (const float*)d_in[9];
    const float* dw_b     = (const float*)d_in[10];
    const float* prelu2_a = (const float*)d_in[11];
    const float* norm2_g  = (const float*)d_in[12];
    const float* norm2_b  = (const float*)d_in[13];
    const float* pw_w     = (const float*)d_in[14];
    float* out = (float*)d_out;

    zero_stats_kernel<<<1, 32>>>();
    gemm1_kernel<<<dim3(MT / 128, HH / 128), 256>>>(x, conv1_w, prelu1_a);
    finalize1_kernel<<<1, MB>>>();
    offdef_kernel<<<dim3(TT / TC, MB), 256>>>(off_dw_w, odc_a, off_pw_w, opc_a,
                                              dw_w, dw_b, prelu2_a, norm1_g, norm1_b);
    finalize2_kernel<<<1, MB>>>();
    gemm2_kernel<<<dim3(MT / 128, BBCH / 128), 256>>>(pw_w, norm2_g, norm2_b, x, out);
}

// round 4
// speedup vs baseline: 2.2258x; 2.2258x over previous
#include <cuda_runtime.h>

// Problem dims
#define MB 8
#define TT 4000
#define BBCH 128
#define HH 512
#define MT (MB*TT)      // 32000 rows
#define LP (TT+4)       // padded length for deform conv (pad_tot = 4)
#define TC 16           // t-tile for fused offset+deform kernel
#define RNUM (TC+5)     // 21 smem rows (t0-2 .. t0+TC+2)

// ---- scratch (device globals; no allocations allowed) ----
__device__ float g_h[MT * HH];     // prelu(x@W1^T), pre-norm   [M*T, H]
__device__ float g_p[MT * HH];     // prelu2(deform out), pre-norm
__device__ float g_sum1[MB], g_sq1[MB], g_sum2[MB], g_sq2[MB];
__device__ float g_mu1[MB], g_iv1[MB], g_mu2[MB], g_iv2[MB];

// ---- tf32 mma helpers ----
__device__ __forceinline__ unsigned f2tf(float f) {
    unsigned u;
    asm("cvt.rna.tf32.f32 %0, %1;" : "=r"(u) : "f"(f));
    return u;
}
__device__ __forceinline__ void mma_tf32(float c[4], const unsigned a[4], const unsigned b[2]) {
    asm volatile(
        "mma.sync.aligned.m16n8k8.row.col.f32.tf32.tf32.f32 "
        "{%0,%1,%2,%3}, {%4,%5,%6,%7}, {%8,%9}, {%0,%1,%2,%3};"
        : "+f"(c[0]), "+f"(c[1]), "+f"(c[2]), "+f"(c[3])
        : "r"(a[0]), "r"(a[1]), "r"(a[2]), "r"(a[3]), "r"(b[0]), "r"(b[1]));
}

// ---------------------------------------------------------------------------
__global__ void zero_stats_kernel() {
    int i = threadIdx.x;
    if (i < MB) { g_sum1[i] = 0.f; g_sq1[i] = 0.f; g_sum2[i] = 0.f; g_sq2[i] = 0.f; }
}

__global__ void finalize1_kernel() {
    int m = threadIdx.x;
    if (m < MB) {
        float n = (float)TT * (float)HH;
        float mu = g_sum1[m] / n;
        float var = g_sq1[m] / n - mu * mu;
        g_mu1[m] = mu;
        g_iv1[m] = 1.0f / sqrtf(var + 1e-8f);
    }
}

__global__ void finalize2_kernel() {
    int m = threadIdx.x;
    if (m < MB) {
        float n = (float)TT * (float)HH;
        float mu = g_sum2[m] / n;
        float var = g_sq2[m] / n - mu * mu;
        g_mu2[m] = mu;
        g_iv2[m] = 1.0f / sqrtf(var + 1e-8f);
    }
}

// ---------------------------------------------------------------------------
// GEMM1 (tf32 tensor cores): h[row,n] = prelu( sum_k x[row,k]*W1[n,k] )
// Block tile 128x128, 8 warps (4 m-warps x 2 n-warps), warp tile 32x64, BK=32.
// Fused per-sample gLN stats of the prelu'd values.
__global__ void __launch_bounds__(256)
gemm1_kernel(const float* __restrict__ A,   // x [32000,128]
             const float* __restrict__ W,   // conv1_w [512,128]
             const float* __restrict__ prelu_a) {
    __shared__ unsigned As[128][36];
    __shared__ unsigned Bs[128][36];
    __shared__ float red[256];
    const int tid = threadIdx.x;
    const int lane = tid & 31, warp = tid >> 5;
    const int warpM = warp & 3, warpN = warp >> 2;
    const int gid = lane >> 2, tig = lane & 3;
    const int rowTile = blockIdx.x * 128, colTile = blockIdx.y * 128;

    float c[2][8][4];
#pragma unroll
    for (int mt = 0; mt < 2; mt++)
#pragma unroll
        for (int nt = 0; nt < 8; nt++)
#pragma unroll
            for (int i = 0; i < 4; i++) c[mt][nt][i] = 0.f;

    for (int k0 = 0; k0 < BBCH; k0 += 32) {
#pragma unroll
        for (int i = 0; i < 16; i++) {
            int e = tid + i * 256;       // 0..4095
            int r = e >> 5, k = e & 31;
            As[r][k] = f2tf(A[(size_t)(rowTile + r) * BBCH + k0 + k]);
            Bs[r][k] = f2tf(W[(size_t)(colTile + r) * BBCH + k0 + k]);
        }
        __syncthreads();
#pragma unroll
        for (int ks = 0; ks < 4; ks++) {
            unsigned b[8][2];
#pragma unroll
            for (int nt = 0; nt < 8; nt++) {
                int n = warpN * 64 + nt * 8 + gid;
                b[nt][0] = Bs[n][ks * 8 + tig];
                b[nt][1] = Bs[n][ks * 8 + tig + 4];
            }
#pragma unroll
            for (int mt = 0; mt < 2; mt++) {
                unsigned a[4];
                int r = warpM * 32 + mt * 16 + gid;
                a[0] = As[r][ks * 8 + tig];
                a[1] = As[r + 8][ks * 8 + tig];
                a[2] = As[r][ks * 8 + tig + 4];
                a[3] = As[r + 8][ks * 8 + tig + 4];
#pragma unroll
                for (int nt = 0; nt < 8; nt++) mma_tf32(c[mt][nt], a, b[nt]);
            }
        }
        __syncthreads();
    }

    // Epilogue: prelu + store + gLN1 stats (two-bin: tile may cross sample boundary)
    const float a = prelu_a[0];
    const int m0 = rowTile / TT;
    const int m1 = (rowTile + 127) / TT;
    float s[2] = {0.f, 0.f}, q[2] = {0.f, 0.f};
#pragma unroll
    for (int mt = 0; mt < 2; mt++) {
        int r0 = rowTile + warpM * 32 + mt * 16 + gid;
        int bin0 = (r0 / TT) - m0;
        int bin8 = ((r0 + 8) / TT) - m0;
#pragma unroll
        for (int nt = 0; nt < 8; nt++) {
            int col = colTile + warpN * 64 + nt * 8 + 2 * tig;
            float v0 = c[mt][nt][0]; v0 = v0 >= 0.f ? v0 : a * v0;
            float v1 = c[mt][nt][1]; v1 = v1 >= 0.f ? v1 : a * v1;
            float v2 = c[mt][nt][2]; v2 = v2 >= 0.f ? v2 : a * v2;
            float v3 = c[mt][nt][3]; v3 = v3 >= 0.f ? v3 : a * v3;
            *(float2*)&g_h[(size_t)r0 * HH + col]       = make_float2(v0, v1);
            *(float2*)&g_h[(size_t)(r0 + 8) * HH + col] = make_float2(v2, v3);
            s[bin0] += v0 + v1;        q[bin0] += v0 * v0 + v1 * v1;
            s[bin8] += v2 + v3;        q[bin8] += v2 * v2 + v3 * v3;
        }
    }
    int nb = (m1 > m0) ? 2 : 1;
    for (int b = 0; b < nb; b++) {
        red[tid] = s[b]; __syncthreads();
        for (int off = 128; off > 0; off >>= 1) {
            if (tid < off) red[tid] += red[tid + off];
            __syncthreads();
        }
        if (tid == 0) atomicAdd(&g_sum1[m0 + b], red[0]);
        __syncthreads();
        red[tid] = q[b]; __syncthreads();
        for (int off = 128; off > 0; off >>= 1) {
            if (tid < off) red[tid] += red[tid + off];
            __syncthreads();
        }
        if (tid == 0) atomicAdd(&g_sq1[m0 + b], red[0]);
        __syncthreads();
    }
}

// ---------------------------------------------------------------------------
// Fused offsets + deformable depthwise conv, t-tiled with smem row cache.
__global__ void __launch_bounds__(256)
offdef_kernel(const float* __restrict__ odww,  // off_dw_w [512,3]
              const float* __restrict__ odc_a,
              const float* __restrict__ opww,  // off_pw_w [3,512]
              const float* __restrict__ opc_a,
              const float* __restrict__ dww,   // dw_w [512,3]
              const float* __restrict__ dwb,   // dw_b [512]
              const float* __restrict__ a2p,   // prelu2_a
              const float* __restrict__ gam,   // norm1_g
              const float* __restrict__ bet) { // norm1_b
    __shared__ float sgc[HH];
    __shared__ float sbc[HH];
    __shared__ float rows[RNUM][HH];
    __shared__ float w0[TC][3], w1[TC][3];
    __shared__ int   i0[TC][3], i1[TC][3];
    __shared__ float red[256];

    const int m  = blockIdx.y;
    const int t0 = blockIdx.x * TC;
    const int tid = threadIdx.x;
    const float mu = g_mu1[m], iv = g_iv1[m];

    for (int c = tid; c < HH; c += 256) {
        float gc = gam[c] * iv;
        sgc[c] = gc;
        sbc[c] = bet[c] - gc * mu;
    }
    __syncthreads();

    const float* base = g_h + (size_t)m * TT * HH;
    for (int e = tid; e < RNUM * HH; e += 256) {
        int j = e >> 9, c = e & 511;
        int src = t0 - 2 + j;
        if (src < 0) src = -src;
        if (src >= TT) src = 2 * TT - 2 - src;
        rows[j][c] = sgc[c] * base[(size_t)src * HH + c] + sbc[c];
    }
    __syncthreads();

    // Phase 1: offsets (16 threads per t)
    {
        const int tyy = tid >> 4, txx = tid & 15;
        const int t = t0 + tyy;
        const float* r0 = rows[tyy + 1];
        const float* r1 = rows[tyy + 2];
        const float* r2 = rows[tyy + 3];
        const float aodc = odc_a[0];
        float s0 = 0.f, s1 = 0.f, s2 = 0.f;
        for (int c = txx; c < HH; c += 16) {
            float od = odww[c * 3] * r0[c] + odww[c * 3 + 1] * r1[c] + odww[c * 3 + 2] * r2[c];
            od = od >= 0.f ? od : aodc * od;
            s0 += opww[c] * od;
            s1 += opww[HH + c] * od;
            s2 += opww[2 * HH + c] * od;
        }
#pragma unroll
        for (int o = 8; o > 0; o >>= 1) {
            s0 += __shfl_down_sync(0xffffffffu, s0, o, 16);
            s1 += __shfl_down_sync(0xffffffffu, s1, o, 16);
            s2 += __shfl_down_sync(0xffffffffu, s2, o, 16);
        }
        if (txx == 0) {
            const float aopc = opc_a[0];
            float off[3];
            off[0] = s0 >= 0.f ? s0 : aopc * s0;
            off[1] = s1 >= 0.f ? s1 : aopc * s1;
            off[2] = s2 >= 0.f ? s2 : aopc * s2;
#pragma unroll
            for (int k = 0; k < 3; k++) {
                float tpos = (float)t + 2.0f * (float)k + off[k];
                tpos = fminf(fmaxf(tpos, (float)t), (float)(t + 4));
                int U = (int)floorf(tpos);
                U = min(U, LP - 2);
                float Uf = (float)U;
                w0[tyy][k] = fmaxf(1.0f - fabsf(Uf - tpos), 0.0f);
                w1[tyy][k] = fmaxf(1.0f - fabsf(Uf + 1.0f - tpos), 0.0f);
                i0[tyy][k] = U - t0;
                i1[tyy][k] = U + 1 - t0;
            }
        }
    }
    __syncthreads();

    // Phase 2: deform depthwise conv + bias + PReLU2 + gLN2 stats
    const float a2 = a2p[0];
    float lsum = 0.f, lsq = 0.f;
    for (int e = tid; e < TC * HH; e += 256) {
        int tyy = e >> 9, h = e & 511;
        float y = dwb[h];
#pragma unroll
        for (int k = 0; k < 3; k++) {
            float v = w0[tyy][k] * rows[i0[tyy][k]][h] + w1[tyy][k] * rows[i1[tyy][k]][h];
            y += dww[h * 3 + k] * v;
        }
        float p = y >= 0.f ? y : a2 * y;
        g_p[(size_t)(m * TT + t0 + tyy) * HH + h] = p;
        lsum += p;
        lsq += p * p;
    }
    red[tid] = lsum; __syncthreads();
    for (int o = 128; o > 0; o >>= 1) {
        if (tid < o) red[tid] += red[tid + o];
        __syncthreads();
    }
    if (tid == 0) atomicAdd(&g_sum2[m], red[0]);
    __syncthreads();
    red[tid] = lsq; __syncthreads();
    for (int o = 128; o > 0; o >>= 1) {
        if (tid < o) red[tid] += red[tid + o];
        __syncthreads();
    }
    if (tid == 0) atomicAdd(&g_sq2[m], red[0]);
}

// ---------------------------------------------------------------------------
// GEMM2 (tf32): out[row,b] = x[row,b] + sum_h W2[b,h]*gln2(g_p[row,h])
// Block tile 128x128 (N=128 fully covered), K=512, gLN fold on A load.
__global__ void __launch_bounds__(256)
gemm2_kernel(const float* __restrict__ W,    // pw_w [128,512]
             const float* __restrict__ gam,  // norm2_g
             const float* __restrict__ bet,  // norm2_b
             const float* __restrict__ X,    // residual x [32000,128]
             float* __restrict__ out) {
    __shared__ unsigned As[128][36];
    __shared__ unsigned Bs[128][36];
    const int tid = threadIdx.x;
    const int lane = tid & 31, warp = tid >> 5;
    const int warpM = warp & 3, warpN = warp >> 2;
    const int gid = lane >> 2, tig = lane & 3;
    const int rowTile = blockIdx.x * 128;

    float c[2][8][4];
#pragma unroll
    for (int mt = 0; mt < 2; mt++)
#pragma unroll
        for (int nt = 0; nt < 8; nt++)
#pragma unroll
            for (int i = 0; i < 4; i++) c[mt][nt][i] = 0.f;

    for (int k0 = 0; k0 < HH; k0 += 32) {
#pragma unroll
        for (int i = 0; i < 16; i++) {
            int e = tid + i * 256;
            int r = e >> 5, k = e & 31;
            int row = rowTile + r;
            int mm = row / TT;
            int kk = k0 + k;
            float gck = gam[kk] * g_iv2[mm];
            float v = g_p[(size_t)row * HH + kk];
            As[r][k] = f2tf(gck * v + bet[kk] - gck * g_mu2[mm]);
            Bs[r][k] = f2tf(W[(size_t)r * HH + kk]);   // r = output channel n
        }
        __syncthreads();
#pragma unroll
        for (int ks = 0; ks < 4; ks++) {
            unsigned b[8][2];
#pragma unroll
            for (int nt = 0; nt < 8; nt++) {
                int n = warpN * 64 + nt * 8 + gid;
                b[nt][0] = Bs[n][ks * 8 + tig];
                b[nt][1] = Bs[n][ks * 8 + tig + 4];
            }
#pragma unroll
            for (int mt = 0; mt < 2; mt++) {
                unsigned a[4];
                int r = warpM * 32 + mt * 16 + gid;
                a[0] = As[r][ks * 8 + tig];
                a[1] = As[r + 8][ks * 8 + tig];
                a[2] = As[r][ks * 8 + tig + 4];
                a[3] = As[r + 8][ks * 8 + tig + 4];
#pragma unroll
                for (int nt = 0; nt < 8; nt++) mma_tf32(c[mt][nt], a, b[nt]);
            }
        }
        __syncthreads();
    }

#pragma unroll
    for (int mt = 0; mt < 2; mt++) {
        int r0 = rowTile + warpM * 32 + mt * 16 + gid;
#pragma unroll
        for (int nt = 0; nt < 8; nt++) {
            int col = warpN * 64 + nt * 8 + 2 * tig;
            float2 x0 = *(const float2*)&X[(size_t)r0 * BBCH + col];
            float2 x8 = *(const float2*)&X[(size_t)(r0 + 8) * BBCH + col];
            *(float2*)&out[(size_t)r0 * BBCH + col] =
                make_float2(c[mt][nt][0] + x0.x, c[mt][nt][1] + x0.y);
            *(float2*)&out[(size_t)(r0 + 8) * BBCH + col] =
                make_float2(c[mt][nt][2] + x8.x, c[mt][nt][3] + x8.y);
        }
    }
}

// ---------------------------------------------------------------------------
extern "C" void kernel_launch(void* const* d_in, const int* in_sizes, int n_in,
                              void* d_out, int out_size) {
    (void)in_sizes; (void)n_in; (void)out_size;
    const float* x        = (const float*)d_in[0];
    const float* conv1_w  = (const float*)d_in[1];
    const float* prelu1_a = (const float*)d_in[2];
    const float* norm1_g  = (const float*)d_in[3];
    const float* norm1_b  = (const float*)d_in[4];
    const float* off_dw_w = (const float*)d_in[5];
    const float* odc_a    = (const float*)d_in[6];
    const float* off_pw_w = (const float*)d_in[7];
    const float* opc_a    = (const float*)d_in[8];
    const float* dw_w     = (const float*)d_in[9];
    const float* dw_b     = (const float*)d_in[10];
    const float* prelu2_a = (const float*)d_in[11];
    const float* norm2_g  = (const float*)d_in[12];
    const float* norm2_b  = (const float*)d_in[13];
    const float* pw_w     = (const float*)d_in[14];
    float* out = (float*)d_out;

    zero_stats_kernel<<<1, 32>>>();
    gemm1_kernel<<<dim3(MT / 128, HH / 128), 256>>>(x, conv1_w, prelu1_a);
    finalize1_kernel<<<1, MB>>>();
    offdef_kernel<<<dim3(TT / TC, MB), 256>>>(off_dw_w, odc_a, off_pw_w, opc_a,
                                              dw_w, dw_b, prelu2_a, norm1_g, norm1_b);
    finalize2_kernel<<<1, MB>>>();
    gemm2_kernel<<<dim3(MT / 128, BBCH / 128), 256>>>(pw_w, norm2_g, norm2_b, x, out);
}

// round 5
// speedup vs baseline: 2.6342x; 1.1835x over previous
#include <cuda_runtime.h>

// Problem dims
#define MB 8
#define TT 4000
#define BBCH 128
#define HH 512
#define MT (MB*TT)      // 32000 rows
#define LP (TT+4)       // padded length for deform conv (pad_tot = 4)
#define TC 16           // t-tile for fused offset+deform kernel
#define RNUM (TC+5)     // 21 smem rows (t0-2 .. t0+TC+2)

// ---- scratch (device globals; no allocations allowed) ----
__device__ float g_h[MT * HH];      // prelu(x@W1^T), pre-norm   [M*T, H]
__device__ float g_p[MT * HH];      // prelu2(deform out), pre-norm
__device__ float g_wg[BBCH * HH];   // pw_w * norm2_g (folded weights)
__device__ float g_S[BBCH], g_C0[BBCH];
__device__ float g_sum1[MB], g_sq1[MB], g_sum2[MB], g_sq2[MB];
__device__ float g_mu1[MB], g_iv1[MB], g_mu2[MB], g_iv2[MB];

// ---- tf32 mma helpers ----
__device__ __forceinline__ unsigned f2tf(float f) {
    unsigned u;
    asm("cvt.rna.tf32.f32 %0, %1;" : "=r"(u) : "f"(f));
    return u;
}
__device__ __forceinline__ void mma_tf32(float c[4], const unsigned a[4], const unsigned b[2]) {
    asm volatile(
        "mma.sync.aligned.m16n8k8.row.col.f32.tf32.tf32.f32 "
        "{%0,%1,%2,%3}, {%4,%5,%6,%7}, {%8,%9}, {%0,%1,%2,%3};"
        : "+f"(c[0]), "+f"(c[1]), "+f"(c[2]), "+f"(c[3])
        : "r"(a[0]), "r"(a[1]), "r"(a[2]), "r"(a[3]), "r"(b[0]), "r"(b[1]));
}

// ---------------------------------------------------------------------------
__global__ void zero_stats_kernel() {
    int i = threadIdx.x;
    if (i < MB) { g_sum1[i] = 0.f; g_sq1[i] = 0.f; g_sum2[i] = 0.f; g_sq2[i] = 0.f; }
}

__global__ void finalize1_kernel() {
    int m = threadIdx.x;
    if (m < MB) {
        float n = (float)TT * (float)HH;
        float mu = g_sum1[m] / n;
        float var = g_sq1[m] / n - mu * mu;
        g_mu1[m] = mu;
        g_iv1[m] = 1.0f / sqrtf(var + 1e-8f);
    }
}

__global__ void finalize2_kernel() {
    int m = threadIdx.x;
    if (m < MB) {
        float n = (float)TT * (float)HH;
        float mu = g_sum2[m] / n;
        float var = g_sq2[m] / n - mu * mu;
        g_mu2[m] = mu;
        g_iv2[m] = 1.0f / sqrtf(var + 1e-8f);
    }
}

// Precompute folded GEMM2 weights: Wg = W2 .* gam (per h), S[b] = sum_h Wg,
// C0[b] = sum_h W2[b,h]*bet[h]. One block per output channel b.
__global__ void wg_kernel(const float* __restrict__ W,    // pw_w [128,512]
                          const float* __restrict__ gam,  // norm2_g
                          const float* __restrict__ bet) { // norm2_b
    const int b = blockIdx.x;
    const int tid = threadIdx.x;   // 128 threads
    __shared__ float rs[128], rc[128];
    float s = 0.f, c0 = 0.f;
    for (int h = tid; h < HH; h += 128) {
        float w = W[(size_t)b * HH + h];
        float wg = w * gam[h];
        g_wg[(size_t)b * HH + h] = wg;
        s += wg;
        c0 += w * bet[h];
    }
    rs[tid] = s; rc[tid] = c0; __syncthreads();
    for (int o = 64; o > 0; o >>= 1) {
        if (tid < o) { rs[tid] += rs[tid + o]; rc[tid] += rc[tid + o]; }
        __syncthreads();
    }
    if (tid == 0) { g_S[b] = rs[0]; g_C0[b] = rc[0]; }
}

// ---------------------------------------------------------------------------
// GEMM1 (tf32): h[row,n] = prelu( sum_k x[row,k]*W1[n,k] ), fused gLN1 stats.
// 128x128 tile, 8 warps, warp tile 32x64, BK=32, register-prefetch pipeline.
__global__ void __launch_bounds__(256)
gemm1_kernel(const float* __restrict__ A,   // x [32000,128]
             const float* __restrict__ W,   // conv1_w [512,128]
             const float* __restrict__ prelu_a) {
    __shared__ unsigned As[128][36];
    __shared__ unsigned Bs[128][36];
    __shared__ float red[256];
    const int tid = threadIdx.x;
    const int lane = tid & 31, warp = tid >> 5;
    const int warpM = warp & 3, warpN = warp >> 2;
    const int gid = lane >> 2, tig = lane & 3;
    const int rowTile = blockIdx.x * 128, colTile = blockIdx.y * 128;

    float c[2][8][4];
#pragma unroll
    for (int mt = 0; mt < 2; mt++)
#pragma unroll
        for (int nt = 0; nt < 8; nt++)
#pragma unroll
            for (int i = 0; i < 4; i++) c[mt][nt][i] = 0.f;

    float fa[16], fb[16];
#pragma unroll
    for (int i = 0; i < 16; i++) {
        int e = tid + i * 256;
        int r = e >> 5, k = e & 31;
        fa[i] = A[(size_t)(rowTile + r) * BBCH + k];
        fb[i] = W[(size_t)(colTile + r) * BBCH + k];
    }

    for (int k0 = 0; k0 < BBCH; k0 += 32) {
#pragma unroll
        for (int i = 0; i < 16; i++) {
            int e = tid + i * 256;
            int r = e >> 5, k = e & 31;
            As[r][k] = f2tf(fa[i]);
            Bs[r][k] = f2tf(fb[i]);
        }
        __syncthreads();
        if (k0 + 32 < BBCH) {
#pragma unroll
            for (int i = 0; i < 16; i++) {
                int e = tid + i * 256;
                int r = e >> 5, k = e & 31;
                fa[i] = A[(size_t)(rowTile + r) * BBCH + k0 + 32 + k];
                fb[i] = W[(size_t)(colTile + r) * BBCH + k0 + 32 + k];
            }
        }
#pragma unroll
        for (int ks = 0; ks < 4; ks++) {
            unsigned b[8][2];
#pragma unroll
            for (int nt = 0; nt < 8; nt++) {
                int n = warpN * 64 + nt * 8 + gid;
                b[nt][0] = Bs[n][ks * 8 + tig];
                b[nt][1] = Bs[n][ks * 8 + tig + 4];
            }
#pragma unroll
            for (int mt = 0; mt < 2; mt++) {
                unsigned a[4];
                int r = warpM * 32 + mt * 16 + gid;
                a[0] = As[r][ks * 8 + tig];
                a[1] = As[r + 8][ks * 8 + tig];
                a[2] = As[r][ks * 8 + tig + 4];
                a[3] = As[r + 8][ks * 8 + tig + 4];
#pragma unroll
                for (int nt = 0; nt < 8; nt++) mma_tf32(c[mt][nt], a, b[nt]);
            }
        }
        __syncthreads();
    }

    // Epilogue: prelu + store + gLN1 stats (tile may straddle one sample boundary)
    const float a = prelu_a[0];
    const int m0 = rowTile / TT;
    const int m1 = (rowTile + 127) / TT;
    const int rowB = (m0 + 1) * TT;
    float s[2] = {0.f, 0.f}, q[2] = {0.f, 0.f};
#pragma unroll
    for (int mt = 0; mt < 2; mt++) {
        int r0 = rowTile + warpM * 32 + mt * 16 + gid;
        int bin0 = (r0 >= rowB) ? 1 : 0;
        int bin8 = (r0 + 8 >= rowB) ? 1 : 0;
#pragma unroll
        for (int nt = 0; nt < 8; nt++) {
            int col = colTile + warpN * 64 + nt * 8 + 2 * tig;
            float v0 = c[mt][nt][0]; v0 = v0 >= 0.f ? v0 : a * v0;
            float v1 = c[mt][nt][1]; v1 = v1 >= 0.f ? v1 : a * v1;
            float v2 = c[mt][nt][2]; v2 = v2 >= 0.f ? v2 : a * v2;
            float v3 = c[mt][nt][3]; v3 = v3 >= 0.f ? v3 : a * v3;
            *(float2*)&g_h[(size_t)r0 * HH + col]       = make_float2(v0, v1);
            *(float2*)&g_h[(size_t)(r0 + 8) * HH + col] = make_float2(v2, v3);
            s[bin0] += v0 + v1;        q[bin0] += v0 * v0 + v1 * v1;
            s[bin8] += v2 + v3;        q[bin8] += v2 * v2 + v3 * v3;
        }
    }
    int nb = (m1 > m0) ? 2 : 1;
    for (int b = 0; b < nb; b++) {
        red[tid] = s[b]; __syncthreads();
        for (int off = 128; off > 0; off >>= 1) {
            if (tid < off) red[tid] += red[tid + off];
            __syncthreads();
        }
        if (tid == 0) atomicAdd(&g_sum1[m0 + b], red[0]);
        __syncthreads();
        red[tid] = q[b]; __syncthreads();
        for (int off = 128; off > 0; off >>= 1) {
            if (tid < off) red[tid] += red[tid + off];
            __syncthreads();
        }
        if (tid == 0) atomicAdd(&g_sq1[m0 + b], red[0]);
        __syncthreads();
    }
}

// ---------------------------------------------------------------------------
// Fused offsets + deformable depthwise conv, t-tiled, fully float4-vectorized.
__global__ void __launch_bounds__(256)
offdef_kernel(const float* __restrict__ odww,  // off_dw_w [512,3]
              const float* __restrict__ odc_a,
              const float* __restrict__ opww,  // off_pw_w [3,512]
              const float* __restrict__ opc_a,
              const float* __restrict__ dww,   // dw_w [512,3]
              const float* __restrict__ dwb,   // dw_b [512]
              const float* __restrict__ a2p,   // prelu2_a
              const float* __restrict__ gam,   // norm1_g
              const float* __restrict__ bet) { // norm1_b
    __shared__ float sgc[HH];
    __shared__ float sbc[HH];
    __shared__ float rows[RNUM * HH];
    __shared__ float w0[TC][3], w1[TC][3];
    __shared__ int   i0[TC][3], i1[TC][3];
    __shared__ float red[256];

    const int m  = blockIdx.y;
    const int t0 = blockIdx.x * TC;
    const int tid = threadIdx.x;
    const float mu = g_mu1[m], iv = g_iv1[m];

    for (int c = tid; c < HH; c += 256) {
        float gc = gam[c] * iv;
        sgc[c] = gc;
        sbc[c] = bet[c] - gc * mu;
    }
    __syncthreads();

    // Stage normalized rows (reflect-mapped), float4.
    const float* base = g_h + (size_t)m * TT * HH;
    for (int e = tid; e < RNUM * (HH / 4); e += 256) {
        int j = e >> 7, c4 = e & 127;
        int src = t0 - 2 + j;
        if (src < 0) src = -src;
        if (src >= TT) src = 2 * TT - 2 - src;
        float4 v = *(const float4*)(base + (size_t)src * HH + c4 * 4);
        float4 g4 = *(const float4*)(sgc + c4 * 4);
        float4 b4 = *(const float4*)(sbc + c4 * 4);
        float4 r;
        r.x = g4.x * v.x + b4.x;
        r.y = g4.y * v.y + b4.y;
        r.z = g4.z * v.z + b4.z;
        r.w = g4.w * v.w + b4.w;
        *(float4*)(rows + j * HH + c4 * 4) = r;
    }
    __syncthreads();

    // Phase 1: offsets (16 threads per t), float4 over channels.
    {
        const int tyy = tid >> 4, txx = tid & 15;
        const int t = t0 + tyy;
        const float* r0 = rows + (tyy + 1) * HH;
        const float* r1 = rows + (tyy + 2) * HH;
        const float* r2 = rows + (tyy + 3) * HH;
        const float aodc = odc_a[0];
        float s0 = 0.f, s1 = 0.f, s2 = 0.f;
#pragma unroll
        for (int it = 0; it < 8; it++) {
            int c = (txx + it * 16) * 4;
            float4 v0 = *(const float4*)(r0 + c);
            float4 v1 = *(const float4*)(r1 + c);
            float4 v2 = *(const float4*)(r2 + c);
            float4 f0 = *(const float4*)(odww + c * 3);
            float4 f1 = *(const float4*)(odww + c * 3 + 4);
            float4 f2 = *(const float4*)(odww + c * 3 + 8);
            float4 p0 = *(const float4*)(opww + c);
            float4 p1 = *(const float4*)(opww + HH + c);
            float4 p2 = *(const float4*)(opww + 2 * HH + c);
            float od;
            od = f0.x * v0.x + f0.y * v1.x + f0.z * v2.x;
            od = od >= 0.f ? od : aodc * od;
            s0 += p0.x * od; s1 += p1.x * od; s2 += p2.x * od;
            od = f0.w * v0.y + f1.x * v1.y + f1.y * v2.y;
            od = od >= 0.f ? od : aodc * od;
            s0 += p0.y * od; s1 += p1.y * od; s2 += p2.y * od;
            od = f1.z * v0.z + f1.w * v1.z + f2.x * v2.z;
            od = od >= 0.f ? od : aodc * od;
            s0 += p0.z * od; s1 += p1.z * od; s2 += p2.z * od;
            od = f2.y * v0.w + f2.z * v1.w + f2.w * v2.w;
            od = od >= 0.f ? od : aodc * od;
            s0 += p0.w * od; s1 += p1.w * od; s2 += p2.w * od;
        }
#pragma unroll
        for (int o = 8; o > 0; o >>= 1) {
            s0 += __shfl_down_sync(0xffffffffu, s0, o, 16);
            s1 += __shfl_down_sync(0xffffffffu, s1, o, 16);
            s2 += __shfl_down_sync(0xffffffffu, s2, o, 16);
        }
        if (txx == 0) {
            const float aopc = opc_a[0];
            float off[3];
            off[0] = s0 >= 0.f ? s0 : aopc * s0;
            off[1] = s1 >= 0.f ? s1 : aopc * s1;
            off[2] = s2 >= 0.f ? s2 : aopc * s2;
#pragma unroll
            for (int k = 0; k < 3; k++) {
                float tpos = (float)t + 2.0f * (float)k + off[k];
                tpos = fminf(fmaxf(tpos, (float)t), (float)(t + 4));
                int U = (int)floorf(tpos);
                U = min(U, LP - 2);
                float Uf = (float)U;
                w0[tyy][k] = fmaxf(1.0f - fabsf(Uf - tpos), 0.0f);
                w1[tyy][k] = fmaxf(1.0f - fabsf(Uf + 1.0f - tpos), 0.0f);
                i0[tyy][k] = U - t0;        // smem row of xp[U]
                i1[tyy][k] = U + 1 - t0;
            }
        }
    }
    __syncthreads();

    // Phase 2: deform depthwise conv + bias + PReLU2 + gLN2 stats, float4.
    const float a2 = a2p[0];
    float lsum = 0.f, lsq = 0.f;
    for (int e = tid; e < TC * (HH / 4); e += 256) {
        int tyy = e >> 7, c = (e & 127) * 4;
        float4 f0 = *(const float4*)(dww + c * 3);
        float4 f1 = *(const float4*)(dww + c * 3 + 4);
        float4 f2 = *(const float4*)(dww + c * 3 + 8);
        float4 sa[3];
#pragma unroll
        for (int k = 0; k < 3; k++) {
            const float* ra = rows + i0[tyy][k] * HH + c;
            const float* rb = rows + i1[tyy][k] * HH + c;
            float4 va = *(const float4*)ra;
            float4 vb = *(const float4*)rb;
            float wa = w0[tyy][k], wb = w1[tyy][k];
            sa[k].x = wa * va.x + wb * vb.x;
            sa[k].y = wa * va.y + wb * vb.y;
            sa[k].z = wa * va.z + wb * vb.z;
            sa[k].w = wa * va.w + wb * vb.w;
        }
        float4 b4 = *(const float4*)(dwb + c);
        float4 y;
        y.x = b4.x + f0.x * sa[0].x + f0.y * sa[1].x + f0.z * sa[2].x;
        y.y = b4.y + f0.w * sa[0].y + f1.x * sa[1].y + f1.y * sa[2].y;
        y.z = b4.z + f1.z * sa[0].z + f1.w * sa[1].z + f2.x * sa[2].z;
        y.w = b4.w + f2.y * sa[0].w + f2.z * sa[1].w + f2.w * sa[2].w;
        y.x = y.x >= 0.f ? y.x : a2 * y.x;
        y.y = y.y >= 0.f ? y.y : a2 * y.y;
        y.z = y.z >= 0.f ? y.z : a2 * y.z;
        y.w = y.w >= 0.f ? y.w : a2 * y.w;
        *(float4*)(g_p + (size_t)(m * TT + t0 + tyy) * HH + c) = y;
        lsum += y.x + y.y + y.z + y.w;
        lsq  += y.x * y.x + y.y * y.y + y.z * y.z + y.w * y.w;
    }
    red[tid] = lsum; __syncthreads();
    for (int o = 128; o > 0; o >>= 1) {
        if (tid < o) red[tid] += red[tid + o];
        __syncthreads();
    }
    if (tid == 0) atomicAdd(&g_sum2[m], red[0]);
    __syncthreads();
    red[tid] = lsq; __syncthreads();
    for (int o = 128; o > 0; o >>= 1) {
        if (tid < o) red[tid] += red[tid + o];
        __syncthreads();
    }
    if (tid == 0) atomicAdd(&g_sq2[m], red[0]);
}

// ---------------------------------------------------------------------------
// GEMM2 (tf32): out[row,b] = x[row,b] + iv2[m]*( (Wg@p)[row,b] - mu2[m]*S[b] ) + C0[b]
// Raw p and pre-folded Wg in the mainloop; gLN applied in the epilogue.
__global__ void __launch_bounds__(256)
gemm2_kernel(const float* __restrict__ X,    // residual x [32000,128]
             float* __restrict__ out) {
    __shared__ unsigned As[128][36];
    __shared__ unsigned Bs[128][36];
    const int tid = threadIdx.x;
    const int lane = tid & 31, warp = tid >> 5;
    const int warpM = warp & 3, warpN = warp >> 2;
    const int gid = lane >> 2, tig = lane & 3;
    const int rowTile = blockIdx.x * 128;

    float c[2][8][4];
#pragma unroll
    for (int mt = 0; mt < 2; mt++)
#pragma unroll
        for (int nt = 0; nt < 8; nt++)
#pragma unroll
            for (int i = 0; i < 4; i++) c[mt][nt][i] = 0.f;

    float fa[16], fb[16];
#pragma unroll
    for (int i = 0; i < 16; i++) {
        int e = tid + i * 256;
        int r = e >> 5, k = e & 31;
        fa[i] = g_p[(size_t)(rowTile + r) * HH + k];
        fb[i] = g_wg[(size_t)r * HH + k];
    }

    for (int k0 = 0; k0 < HH; k0 += 32) {
#pragma unroll
        for (int i = 0; i < 16; i++) {
            int e = tid + i * 256;
            int r = e >> 5, k = e & 31;
            As[r][k] = f2tf(fa[i]);
            Bs[r][k] = f2tf(fb[i]);
        }
        __syncthreads();
        if (k0 + 32 < HH) {
#pragma unroll
            for (int i = 0; i < 16; i++) {
                int e = tid + i * 256;
                int r = e >> 5, k = e & 31;
                fa[i] = g_p[(size_t)(rowTile + r) * HH + k0 + 32 + k];
                fb[i] = g_wg[(size_t)r * HH + k0 + 32 + k];
            }
        }
#pragma unroll
        for (int ks = 0; ks < 4; ks++) {
            unsigned b[8][2];
#pragma unroll
            for (int nt = 0; nt < 8; nt++) {
                int n = warpN * 64 + nt * 8 + gid;
                b[nt][0] = Bs[n][ks * 8 + tig];
                b[nt][1] = Bs[n][ks * 8 + tig + 4];
            }
#pragma unroll
            for (int mt = 0; mt < 2; mt++) {
                unsigned a[4];
                int r = warpM * 32 + mt * 16 + gid;
                a[0] = As[r][ks * 8 + tig];
                a[1] = As[r + 8][ks * 8 + tig];
                a[2] = As[r][ks * 8 + tig + 4];
                a[3] = As[r + 8][ks * 8 + tig + 4];
#pragma unroll
                for (int nt = 0; nt < 8; nt++) mma_tf32(c[mt][nt], a, b[nt]);
            }
        }
        __syncthreads();
    }

    const int m0 = rowTile / TT;
    const int rowB = (m0 + 1) * TT;
#pragma unroll
    for (int mt = 0; mt < 2; mt++) {
        int r0 = rowTile + warpM * 32 + mt * 16 + gid;
        int mmA = (r0 >= rowB) ? m0 + 1 : m0;
        int mmB = (r0 + 8 >= rowB) ? m0 + 1 : m0;
        float ivA = g_iv2[mmA], muA = g_mu2[mmA];
        float ivB = g_iv2[mmB], muB = g_mu2[mmB];
#pragma unroll
        for (int nt = 0; nt < 8; nt++) {
            int col = warpN * 64 + nt * 8 + 2 * tig;
            float S0 = g_S[col], S1 = g_S[col + 1];
            float C00 = g_C0[col], C01 = g_C0[col + 1];
            float2 x0 = *(const float2*)&X[(size_t)r0 * BBCH + col];
            float2 x8 = *(const float2*)&X[(size_t)(r0 + 8) * BBCH + col];
            *(float2*)&out[(size_t)r0 * BBCH + col] = make_float2(
                ivA * (c[mt][nt][0] - muA * S0) + C00 + x0.x,
                ivA * (c[mt][nt][1] - muA * S1) + C01 + x0.y);
            *(float2*)&out[(size_t)(r0 + 8) * BBCH + col] = make_float2(
                ivB * (c[mt][nt][2] - muB * S0) + C00 + x8.x,
                ivB * (c[mt][nt][3] - muB * S1) + C01 + x8.y);
        }
    }
}

// ---------------------------------------------------------------------------
extern "C" void kernel_launch(void* const* d_in, const int* in_sizes, int n_in,
                              void* d_out, int out_size) {
    (void)in_sizes; (void)n_in; (void)out_size;
    const float* x        = (const float*)d_in[0];
    const float* conv1_w  = (const float*)d_in[1];
    const float* prelu1_a = (const float*)d_in[2];
    const float* norm1_g  = (const float*)d_in[3];
    const float* norm1_b  = (const float*)d_in[4];
    const float* off_dw_w = (const float*)d_in[5];
    const float* odc_a    = (const float*)d_in[6];
    const float* off_pw_w = (const float*)d_in[7];
    const float* opc_a    = (const float*)d_in[8];
    const float* dw_w     = (const float*)d_in[9];
    const float* dw_b     = (const float*)d_in[10];
    const float* prelu2_a = (const float*)d_in[11];
    const float* norm2_g  = (const float*)d_in[12];
    const float* norm2_b  = (const float*)d_in[13];
    const float* pw_w     = (const float*)d_in[14];
    float* out = (float*)d_out;

    zero_stats_kernel<<<1, 32>>>();
    wg_kernel<<<BBCH, 128>>>(pw_w, norm2_g, norm2_b);
    gemm1_kernel<<<dim3(MT / 128, HH / 128), 256>>>(x, conv1_w, prelu1_a);
    finalize1_kernel<<<1, MB>>>();
    offdef_kernel<<<dim3(TT / TC, MB), 256>>>(off_dw_w, odc_a, off_pw_w, opc_a,
                                              dw_w, dw_b, prelu2_a, norm1_g, norm1_b);
    finalize2_kernel<<<1, MB>>>();
    gemm2_kernel<<<dim3(MT / 128, BBCH / 128), 256>>>(x, out);
}

// round 6
// speedup vs baseline: 2.9261x; 1.1108x over previous
#include <cuda_runtime.h>

// Problem dims
#define MB 8
#define TT 4000
#define BBCH 128
#define HH 512
#define MT (MB*TT)      // 32000 rows
#define LP (TT+4)       // padded length for deform conv (pad_tot = 4)
#define TC 16           // t-tile for fused offset+deform kernel
#define RNUM (TC+5)     // 21 smem rows (t0-2 .. t0+TC+2)

// ---- scratch (device globals; no allocations allowed) ----
__device__ float g_h[MT * HH];      // prelu(x@W1^T), pre-norm   [M*T, H]
__device__ float g_p[MT * HH];      // prelu2(deform out), pre-norm
__device__ float g_wg[BBCH * HH];   // pw_w * norm2_g (folded weights)
__device__ float g_S[BBCH], g_C0[BBCH];
__device__ float g_sum1[MB], g_sq1[MB], g_sum2[MB], g_sq2[MB];

// ---- tf32 mma helpers ----
__device__ __forceinline__ unsigned f2tf(float f) {
    unsigned u;
    asm("cvt.rna.tf32.f32 %0, %1;" : "=r"(u) : "f"(f));
    return u;
}
__device__ __forceinline__ void mma_tf32(float c[4], const unsigned a[4], const unsigned b[2]) {
    asm volatile(
        "mma.sync.aligned.m16n8k8.row.col.f32.tf32.tf32.f32 "
        "{%0,%1,%2,%3}, {%4,%5,%6,%7}, {%8,%9}, {%0,%1,%2,%3};"
        : "+f"(c[0]), "+f"(c[1]), "+f"(c[2]), "+f"(c[3])
        : "r"(a[0]), "r"(a[1]), "r"(a[2]), "r"(a[3]), "r"(b[0]), "r"(b[1]));
}

// ---------------------------------------------------------------------------
// Precompute folded GEMM2 weights + zero the stat accumulators.
// Wg = W2 .* gam (per h), S[b] = sum_h Wg, C0[b] = sum_h W2[b,h]*bet[h].
__global__ void wg_kernel(const float* __restrict__ W,     // pw_w [128,512]
                          const float* __restrict__ gam,   // norm2_g
                          const float* __restrict__ bet) { // norm2_b
    const int b = blockIdx.x;
    const int tid = threadIdx.x;   // 128 threads
    if (b == 0 && tid < MB) {
        g_sum1[tid] = 0.f; g_sq1[tid] = 0.f;
        g_sum2[tid] = 0.f; g_sq2[tid] = 0.f;
    }
    __shared__ float rs[128], rc[128];
    float s = 0.f, c0 = 0.f;
    for (int h = tid; h < HH; h += 128) {
        float w = W[(size_t)b * HH + h];
        float wg = w * gam[h];
        g_wg[(size_t)b * HH + h] = wg;
        s += wg;
        c0 += w * bet[h];
    }
    rs[tid] = s; rc[tid] = c0; __syncthreads();
    for (int o = 64; o > 0; o >>= 1) {
        if (tid < o) { rs[tid] += rs[tid + o]; rc[tid] += rc[tid + o]; }
        __syncthreads();
    }
    if (tid == 0) { g_S[b] = rs[0]; g_C0[b] = rc[0]; }
}

// ---------------------------------------------------------------------------
// GEMM1 (tf32): h[row,n] = prelu( sum_k x[row,k]*W1[n,k] ), fused gLN1 stats.
// 128x128 tile, 8 warps, warp tile 32x64, BK=32, float4 staging + reg prefetch.
__global__ void __launch_bounds__(256)
gemm1_kernel(const float* __restrict__ A,   // x [32000,128]
             const float* __restrict__ W,   // conv1_w [512,128]
             const float* __restrict__ prelu_a) {
    __shared__ unsigned As[128][36];
    __shared__ unsigned Bs[128][36];
    __shared__ float red[256];
    const int tid = threadIdx.x;
    const int lane = tid & 31, warp = tid >> 5;
    const int warpM = warp & 3, warpN = warp >> 2;
    const int gid = lane >> 2, tig = lane & 3;
    const int rowTile = blockIdx.x * 128, colTile = blockIdx.y * 128;

    float c[2][8][4];
#pragma unroll
    for (int mt = 0; mt < 2; mt++)
#pragma unroll
        for (int nt = 0; nt < 8; nt++)
#pragma unroll
            for (int i = 0; i < 4; i++) c[mt][nt][i] = 0.f;

    // float4 staging: 1024 float4 slots per tile, 4 per thread.
    float4 fa[4], fb[4];
#pragma unroll
    for (int i = 0; i < 4; i++) {
        int s = tid + i * 256;
        int r = s >> 3, kq = s & 7;
        fa[i] = *(const float4*)&A[(size_t)(rowTile + r) * BBCH + kq * 4];
        fb[i] = *(const float4*)&W[(size_t)(colTile + r) * BBCH + kq * 4];
    }

    for (int k0 = 0; k0 < BBCH; k0 += 32) {
#pragma unroll
        for (int i = 0; i < 4; i++) {
            int s = tid + i * 256;
            int r = s >> 3, kq = s & 7;
            uint4 ua, ub;
            ua.x = f2tf(fa[i].x); ua.y = f2tf(fa[i].y); ua.z = f2tf(fa[i].z); ua.w = f2tf(fa[i].w);
            ub.x = f2tf(fb[i].x); ub.y = f2tf(fb[i].y); ub.z = f2tf(fb[i].z); ub.w = f2tf(fb[i].w);
            *(uint4*)&As[r][kq * 4] = ua;
            *(uint4*)&Bs[r][kq * 4] = ub;
        }
        __syncthreads();
        if (k0 + 32 < BBCH) {
#pragma unroll
            for (int i = 0; i < 4; i++) {
                int s = tid + i * 256;
                int r = s >> 3, kq = s & 7;
                fa[i] = *(const float4*)&A[(size_t)(rowTile + r) * BBCH + k0 + 32 + kq * 4];
                fb[i] = *(const float4*)&W[(size_t)(colTile + r) * BBCH + k0 + 32 + kq * 4];
            }
        }
#pragma unroll
        for (int ks = 0; ks < 4; ks++) {
            unsigned b[8][2];
#pragma unroll
            for (int nt = 0; nt < 8; nt++) {
                int n = warpN * 64 + nt * 8 + gid;
                b[nt][0] = Bs[n][ks * 8 + tig];
                b[nt][1] = Bs[n][ks * 8 + tig + 4];
            }
#pragma unroll
            for (int mt = 0; mt < 2; mt++) {
                unsigned a[4];
                int r = warpM * 32 + mt * 16 + gid;
                a[0] = As[r][ks * 8 + tig];
                a[1] = As[r + 8][ks * 8 + tig];
                a[2] = As[r][ks * 8 + tig + 4];
                a[3] = As[r + 8][ks * 8 + tig + 4];
#pragma unroll
                for (int nt = 0; nt < 8; nt++) mma_tf32(c[mt][nt], a, b[nt]);
            }
        }
        __syncthreads();
    }

    // Epilogue: prelu + store + gLN1 stats (tile may straddle one sample boundary)
    const float a = prelu_a[0];
    const int m0 = rowTile / TT;
    const int m1 = (rowTile + 127) / TT;
    const int rowB = (m0 + 1) * TT;
    float s[2] = {0.f, 0.f}, q[2] = {0.f, 0.f};
#pragma unroll
    for (int mt = 0; mt < 2; mt++) {
        int r0 = rowTile + warpM * 32 + mt * 16 + gid;
        int bin0 = (r0 >= rowB) ? 1 : 0;
        int bin8 = (r0 + 8 >= rowB) ? 1 : 0;
#pragma unroll
        for (int nt = 0; nt < 8; nt++) {
            int col = colTile + warpN * 64 + nt * 8 + 2 * tig;
            float v0 = c[mt][nt][0]; v0 = v0 >= 0.f ? v0 : a * v0;
            float v1 = c[mt][nt][1]; v1 = v1 >= 0.f ? v1 : a * v1;
            float v2 = c[mt][nt][2]; v2 = v2 >= 0.f ? v2 : a * v2;
            float v3 = c[mt][nt][3]; v3 = v3 >= 0.f ? v3 : a * v3;
            *(float2*)&g_h[(size_t)r0 * HH + col]       = make_float2(v0, v1);
            *(float2*)&g_h[(size_t)(r0 + 8) * HH + col] = make_float2(v2, v3);
            s[bin0] += v0 + v1;        q[bin0] += v0 * v0 + v1 * v1;
            s[bin8] += v2 + v3;        q[bin8] += v2 * v2 + v3 * v3;
        }
    }
    int nb = (m1 > m0) ? 2 : 1;
    for (int b = 0; b < nb; b++) {
        red[tid] = s[b]; __syncthreads();
        for (int off = 128; off > 0; off >>= 1) {
            if (tid < off) red[tid] += red[tid + off];
            __syncthreads();
        }
        if (tid == 0) atomicAdd(&g_sum1[m0 + b], red[0]);
        __syncthreads();
        red[tid] = q[b]; __syncthreads();
        for (int off = 128; off > 0; off >>= 1) {
            if (tid < off) red[tid] += red[tid + off];
            __syncthreads();
        }
        if (tid == 0) atomicAdd(&g_sq1[m0 + b], red[0]);
        __syncthreads();
    }
}

// ---------------------------------------------------------------------------
// Fused offsets + deformable depthwise conv, t-tiled, float4-vectorized.
// Computes mu1/iv1 inline from the gemm1 stat accumulators.
__global__ void __launch_bounds__(256)
offdef_kernel(const float* __restrict__ odww,  // off_dw_w [512,3]
              const float* __restrict__ odc_a,
              const float* __restrict__ opww,  // off_pw_w [3,512]
              const float* __restrict__ opc_a,
              const float* __restrict__ dww,   // dw_w [512,3]
              const float* __restrict__ dwb,   // dw_b [512]
              const float* __restrict__ a2p,   // prelu2_a
              const float* __restrict__ gam,   // norm1_g
              const float* __restrict__ bet) { // norm1_b
    __shared__ float sgc[HH];
    __shared__ float sbc[HH];
    __shared__ float rows[RNUM * HH];
    __shared__ float w0[TC][3], w1[TC][3];
    __shared__ int   i0[TC][3], i1[TC][3];
    __shared__ float red[256];

    const int m  = blockIdx.y;
    const int t0 = blockIdx.x * TC;
    const int tid = threadIdx.x;
    const float nrm = (float)TT * (float)HH;
    const float mu = g_sum1[m] / nrm;
    const float iv = 1.0f / sqrtf(g_sq1[m] / nrm - mu * mu + 1e-8f);

    for (int c = tid; c < HH; c += 256) {
        float gc = gam[c] * iv;
        sgc[c] = gc;
        sbc[c] = bet[c] - gc * mu;
    }
    __syncthreads();

    // Stage normalized rows (reflect-mapped), float4.
    const float* base = g_h + (size_t)m * TT * HH;
    for (int e = tid; e < RNUM * (HH / 4); e += 256) {
        int j = e >> 7, c4 = e & 127;
        int src = t0 - 2 + j;
        if (src < 0) src = -src;
        if (src >= TT) src = 2 * TT - 2 - src;
        float4 v = *(const float4*)(base + (size_t)src * HH + c4 * 4);
        float4 g4 = *(const float4*)(sgc + c4 * 4);
        float4 b4 = *(const float4*)(sbc + c4 * 4);
        float4 r;
        r.x = g4.x * v.x + b4.x;
        r.y = g4.y * v.y + b4.y;
        r.z = g4.z * v.z + b4.z;
        r.w = g4.w * v.w + b4.w;
        *(float4*)(rows + j * HH + c4 * 4) = r;
    }
    __syncthreads();

    // Phase 1: offsets (16 threads per t), float4 over channels.
    {
        const int tyy = tid >> 4, txx = tid & 15;
        const int t = t0 + tyy;
        const float* r0 = rows + (tyy + 1) * HH;
        const float* r1 = rows + (tyy + 2) * HH;
        const float* r2 = rows + (tyy + 3) * HH;
        const float aodc = odc_a[0];
        float s0 = 0.f, s1 = 0.f, s2 = 0.f;
#pragma unroll
        for (int it = 0; it < 8; it++) {
            int c = (txx + it * 16) * 4;
            float4 v0 = *(const float4*)(r0 + c);
            float4 v1 = *(const float4*)(r1 + c);
            float4 v2 = *(const float4*)(r2 + c);
            float4 f0 = *(const float4*)(odww + c * 3);
            float4 f1 = *(const float4*)(odww + c * 3 + 4);
            float4 f2 = *(const float4*)(odww + c * 3 + 8);
            float4 p0 = *(const float4*)(opww + c);
            float4 p1 = *(const float4*)(opww + HH + c);
            float4 p2 = *(const float4*)(opww + 2 * HH + c);
            float od;
            od = f0.x * v0.x + f0.y * v1.x + f0.z * v2.x;
            od = od >= 0.f ? od : aodc * od;
            s0 += p0.x * od; s1 += p1.x * od; s2 += p2.x * od;
            od = f0.w * v0.y + f1.x * v1.y + f1.y * v2.y;
            od = od >= 0.f ? od : aodc * od;
            s0 += p0.y * od; s1 += p1.y * od; s2 += p2.y * od;
            od = f1.z * v0.z + f1.w * v1.z + f2.x * v2.z;
            od = od >= 0.f ? od : aodc * od;
            s0 += p0.z * od; s1 += p1.z * od; s2 += p2.z * od;
            od = f2.y * v0.w + f2.z * v1.w + f2.w * v2.w;
            od = od >= 0.f ? od : aodc * od;
            s0 += p0.w * od; s1 += p1.w * od; s2 += p2.w * od;
        }
#pragma unroll
        for (int o = 8; o > 0; o >>= 1) {
            s0 += __shfl_down_sync(0xffffffffu, s0, o, 16);
            s1 += __shfl_down_sync(0xffffffffu, s1, o, 16);
            s2 += __shfl_down_sync(0xffffffffu, s2, o, 16);
        }
        if (txx == 0) {
            const float aopc = opc_a[0];
            float off[3];
            off[0] = s0 >= 0.f ? s0 : aopc * s0;
            off[1] = s1 >= 0.f ? s1 : aopc * s1;
            off[2] = s2 >= 0.f ? s2 : aopc * s2;
#pragma unroll
            for (int k = 0; k < 3; k++) {
                float tpos = (float)t + 2.0f * (float)k + off[k];
                tpos = fminf(fmaxf(tpos, (float)t), (float)(t + 4));
                int U = (int)floorf(tpos);
                U = min(U, LP - 2);
                float Uf = (float)U;
                w0[tyy][k] = fmaxf(1.0f - fabsf(Uf - tpos), 0.0f);
                w1[tyy][k] = fmaxf(1.0f - fabsf(Uf + 1.0f - tpos), 0.0f);
                i0[tyy][k] = U - t0;        // smem row of xp[U]
                i1[tyy][k] = U + 1 - t0;
            }
        }
    }
    __syncthreads();

    // Phase 2: deform depthwise conv + bias + PReLU2 + gLN2 stats, float4.
    const float a2 = a2p[0];
    float lsum = 0.f, lsq = 0.f;
    for (int e = tid; e < TC * (HH / 4); e += 256) {
        int tyy = e >> 7, c = (e & 127) * 4;
        float4 f0 = *(const float4*)(dww + c * 3);
        float4 f1 = *(const float4*)(dww + c * 3 + 4);
        float4 f2 = *(const float4*)(dww + c * 3 + 8);
        float4 sa[3];
#pragma unroll
        for (int k = 0; k < 3; k++) {
            const float* ra = rows + i0[tyy][k] * HH + c;
            const float* rb = rows + i1[tyy][k] * HH + c;
            float4 va = *(const float4*)ra;
            float4 vb = *(const float4*)rb;
            float wa = w0[tyy][k], wb = w1[tyy][k];
            sa[k].x = wa * va.x + wb * vb.x;
            sa[k].y = wa * va.y + wb * vb.y;
            sa[k].z = wa * va.z + wb * vb.z;
            sa[k].w = wa * va.w + wb * vb.w;
        }
        float4 b4 = *(const float4*)(dwb + c);
        float4 y;
        y.x = b4.x + f0.x * sa[0].x + f0.y * sa[1].x + f0.z * sa[2].x;
        y.y = b4.y + f0.w * sa[0].y + f1.x * sa[1].y + f1.y * sa[2].y;
        y.z = b4.z + f1.z * sa[0].z + f1.w * sa[1].z + f2.x * sa[2].z;
        y.w = b4.w + f2.y * sa[0].w + f2.z * sa[1].w + f2.w * sa[2].w;
        y.x = y.x >= 0.f ? y.x : a2 * y.x;
        y.y = y.y >= 0.f ? y.y : a2 * y.y;
        y.z = y.z >= 0.f ? y.z : a2 * y.z;
        y.w = y.w >= 0.f ? y.w : a2 * y.w;
        *(float4*)(g_p + (size_t)(m * TT + t0 + tyy) * HH + c) = y;
        lsum += y.x + y.y + y.z + y.w;
        lsq  += y.x * y.x + y.y * y.y + y.z * y.z + y.w * y.w;
    }
    red[tid] = lsum; __syncthreads();
    for (int o = 128; o > 0; o >>= 1) {
        if (tid < o) red[tid] += red[tid + o];
        __syncthreads();
    }
    if (tid == 0) atomicAdd(&g_sum2[m], red[0]);
    __syncthreads();
    red[tid] = lsq; __syncthreads();
    for (int o = 128; o > 0; o >>= 1) {
        if (tid < o) red[tid] += red[tid + o];
        __syncthreads();
    }
    if (tid == 0) atomicAdd(&g_sq2[m], red[0]);
}

// ---------------------------------------------------------------------------
// GEMM2 (tf32): out[row,b] = x[row,b] + iv2[m]*( (Wg@p)[row,b] - mu2[m]*S[b] ) + C0[b]
// Raw p and pre-folded Wg in the mainloop; gLN (stats computed inline) in epilogue.
__global__ void __launch_bounds__(256)
gemm2_kernel(const float* __restrict__ X,    // residual x [32000,128]
             float* __restrict__ out) {
    __shared__ unsigned As[128][36];
    __shared__ unsigned Bs[128][36];
    const int tid = threadIdx.x;
    const int lane = tid & 31, warp = tid >> 5;
    const int warpM = warp & 3, warpN = warp >> 2;
    const int gid = lane >> 2, tig = lane & 3;
    const int rowTile = blockIdx.x * 128;

    float c[2][8][4];
#pragma unroll
    for (int mt = 0; mt < 2; mt++)
#pragma unroll
        for (int nt = 0; nt < 8; nt++)
#pragma unroll
            for (int i = 0; i < 4; i++) c[mt][nt][i] = 0.f;

    float4 fa[4], fb[4];
#pragma unroll
    for (int i = 0; i < 4; i++) {
        int s = tid + i * 256;
        int r = s >> 3, kq = s & 7;
        fa[i] = *(const float4*)&g_p[(size_t)(rowTile + r) * HH + kq * 4];
        fb[i] = *(const float4*)&g_wg[(size_t)r * HH + kq * 4];
    }

    for (int k0 = 0; k0 < HH; k0 += 32) {
#pragma unroll
        for (int i = 0; i < 4; i++) {
            int s = tid + i * 256;
            int r = s >> 3, kq = s & 7;
            uint4 ua, ub;
            ua.x = f2tf(fa[i].x); ua.y = f2tf(fa[i].y); ua.z = f2tf(fa[i].z); ua.w = f2tf(fa[i].w);
            ub.x = f2tf(fb[i].x); ub.y = f2tf(fb[i].y); ub.z = f2tf(fb[i].z); ub.w = f2tf(fb[i].w);
            *(uint4*)&As[r][kq * 4] = ua;
            *(uint4*)&Bs[r][kq * 4] = ub;
        }
        __syncthreads();
        if (k0 + 32 < HH) {
#pragma unroll
            for (int i = 0; i < 4; i++) {
                int s = tid + i * 256;
                int r = s >> 3, kq = s & 7;
                fa[i] = *(const float4*)&g_p[(size_t)(rowTile + r) * HH + k0 + 32 + kq * 4];
                fb[i] = *(const float4*)&g_wg[(size_t)r * HH + k0 + 32 + kq * 4];
            }
        }
#pragma unroll
        for (int ks = 0; ks < 4; ks++) {
            unsigned b[8][2];
#pragma unroll
            for (int nt = 0; nt < 8; nt++) {
                int n = warpN * 64 + nt * 8 + gid;
                b[nt][0] = Bs[n][ks * 8 + tig];
                b[nt][1] = Bs[n][ks * 8 + tig + 4];
            }
#pragma unroll
            for (int mt = 0; mt < 2; mt++) {
                unsigned a[4];
                int r = warpM * 32 + mt * 16 + gid;
                a[0] = As[r][ks * 8 + tig];
                a[1] = As[r + 8][ks * 8 + tig];
                a[2] = As[r][ks * 8 + tig + 4];
                a[3] = As[r + 8][ks * 8 + tig + 4];
#pragma unroll
                for (int nt = 0; nt < 8; nt++) mma_tf32(c[mt][nt], a, b[nt]);
            }
        }
        __syncthreads();
    }

    const int m0 = rowTile / TT;
    const int rowB = (m0 + 1) * TT;
    const float nrm = (float)TT * (float)HH;
#pragma unroll
    for (int mt = 0; mt < 2; mt++) {
        int r0 = rowTile + warpM * 32 + mt * 16 + gid;
        int mmA = (r0 >= rowB) ? m0 + 1 : m0;
        int mmB = (r0 + 8 >= rowB) ? m0 + 1 : m0;
        float muA = g_sum2[mmA] / nrm;
        float ivA = 1.0f / sqrtf(g_sq2[mmA] / nrm - muA * muA + 1e-8f);
        float muB = g_sum2[mmB] / nrm;
        float ivB = 1.0f / sqrtf(g_sq2[mmB] / nrm - muB * muB + 1e-8f);
#pragma unroll
        for (int nt = 0; nt < 8; nt++) {
            int col = warpN * 64 + nt * 8 + 2 * tig;
            float S0 = g_S[col], S1 = g_S[col + 1];
            float C00 = g_C0[col], C01 = g_C0[col + 1];
            float2 x0 = *(const float2*)&X[(size_t)r0 * BBCH + col];
            float2 x8 = *(const float2*)&X[(size_t)(r0 + 8) * BBCH + col];
            *(float2*)&out[(size_t)r0 * BBCH + col] = make_float2(
                ivA * (c[mt][nt][0] - muA * S0) + C00 + x0.x,
                ivA * (c[mt][nt][1] - muA * S1) + C01 + x0.y);
            *(float2*)&out[(size_t)(r0 + 8) * BBCH + col] = make_float2(
                ivB * (c[mt][nt][2] - muB * S0) + C00 + x8.x,
                ivB * (c[mt][nt][3] - muB * S1) + C01 + x8.y);
        }
    }
}

// ---------------------------------------------------------------------------
extern "C" void kernel_launch(void* const* d_in, const int* in_sizes, int n_in,
                              void* d_out, int out_size) {
    (void)in_sizes; (void)n_in; (void)out_size;
    const float* x        = (const float*)d_in[0];
    const float* conv1_w  = (const float*)d_in[1];
    const float* prelu1_a = (const float*)d_in[2];
    const float* norm1_g  = (const float*)d_in[3];
    const float* norm1_b  = (const float*)d_in[4];
    const float* off_dw_w = (const float*)d_in[5];
    const float* odc_a    = (const float*)d_in[6];
    const float* off_pw_w = (const float*)d_in[7];
    const float* opc_a    = (const float*)d_in[8];
    const float* dw_w     = (const float*)d_in[9];
    const float* dw_b     = (const float*)d_in[10];
    const float* prelu2_a = (const float*)d_in[11];
    const float* norm2_g  = (const float*)d_in[12];
    const float* norm2_b  = (const float*)d_in[13];
    const float* pw_w     = (const float*)d_in[14];
    float* out = (float*)d_out;

    wg_kernel<<<BBCH, 128>>>(pw_w, norm2_g, norm2_b);
    gemm1_kernel<<<dim3(MT / 128, HH / 128), 256>>>(x, conv1_w, prelu1_a);
    offdef_kernel<<<dim3(TT / TC, MB), 256>>>(off_dw_w, odc_a, off_pw_w, opc_a,
                                              dw_w, dw_b, prelu2_a, norm1_g, norm1_b);
    gemm2_kernel<<<dim3(MT / 128, BBCH / 128), 256>>>(x, out);
}